// round 1
// baseline (speedup 1.0000x reference)
#include <cuda_runtime.h>
#include <cuda_bf16.h>
#include <math.h>

// Problem constants
#define B_  16
#define S_  512
#define HID_ 768
#define NH_ 4
#define HD_ 192          // head dim
#define NL_ 9            // labels
#define M_ROWS (B_ * S_) // 8192
#define BH_ (B_ * NH_)   // 64
#define INV_SQRT_D 0.07216878364870323f  // 1/sqrt(192)

// -------- device scratch (static; no allocations allowed) --------
__device__ float g_q[M_ROWS * HID_];
__device__ float g_k[M_ROWS * HID_];
__device__ float g_v[M_ROWS * HID_];
__device__ float g_s[(size_t)BH_ * S_ * S_];   // 64 MB attention scores/probs
__device__ float g_c[M_ROWS * HID_];           // context
__device__ float g_h[M_ROWS * HID_];           // residual + LN output

// ============================================================
// Tiled SGEMM: C[m,n] = sum_k A[m,k]*B[k,n] + bias[n] (+ resid[m,n])
// BM=BN=64, BK=16, 256 threads, 4x4 per thread.
// M % 64 == 0, N % 64 == 0, K % 16 == 0 (all true for our shapes).
// ============================================================
#define BM 64
#define BN 64
#define BK 16

__device__ __forceinline__ void gemm_nn_body(
    const float* __restrict__ A, int lda,
    const float* __restrict__ B, int ldb,
    const float* __restrict__ bias,
    const float* __restrict__ resid, int ldr,
    float* __restrict__ C, int ldc,
    int K, int bm, int bn)
{
    __shared__ float As[BM][BK + 1];
    __shared__ float Bs[BK][BN];

    const int tid = threadIdx.x;
    const int tx = tid & 15;
    const int ty = tid >> 4;

    float acc[4][4] = {};

    for (int k0 = 0; k0 < K; k0 += BK) {
        // load A tile 64x16 (float4 per thread)
        {
            int m = tid >> 2;
            int k = (tid & 3) << 2;
            float4 a4 = *(const float4*)(A + (size_t)(bm + m) * lda + k0 + k);
            As[m][k + 0] = a4.x; As[m][k + 1] = a4.y;
            As[m][k + 2] = a4.z; As[m][k + 3] = a4.w;
        }
        // load B tile 16x64
        {
            int k = tid >> 4;
            int n = (tid & 15) << 2;
            float4 b4 = *(const float4*)(B + (size_t)(k0 + k) * ldb + bn + n);
            *(float4*)&Bs[k][n] = b4;
        }
        __syncthreads();

        #pragma unroll
        for (int kk = 0; kk < BK; ++kk) {
            float a[4], b[4];
            #pragma unroll
            for (int i = 0; i < 4; i++) a[i] = As[ty * 4 + i][kk];
            #pragma unroll
            for (int j = 0; j < 4; j++) b[j] = Bs[kk][tx * 4 + j];
            #pragma unroll
            for (int i = 0; i < 4; i++)
                #pragma unroll
                for (int j = 0; j < 4; j++)
                    acc[i][j] = fmaf(a[i], b[j], acc[i][j]);
        }
        __syncthreads();
    }

    #pragma unroll
    for (int i = 0; i < 4; i++) {
        int m = bm + ty * 4 + i;
        #pragma unroll
        for (int j = 0; j < 4; j++) {
            int n = bn + tx * 4 + j;
            float v = acc[i][j];
            if (bias)  v += bias[n];
            if (resid) v += resid[(size_t)m * ldr + n];
            C[(size_t)m * ldc + n] = v;
        }
    }
}

__global__ __launch_bounds__(256) void gemm_nn_kernel(
    const float* __restrict__ A, int lda,
    const float* __restrict__ B, int ldb,
    const float* __restrict__ bias,
    const float* __restrict__ resid, int ldr,
    float* __restrict__ C, int ldc, int K)
{
    gemm_nn_body(A, lda, B, ldb, bias, resid, ldr, C, ldc, K,
                 blockIdx.y * BM, blockIdx.x * BN);
}

// ============================================================
// Scores: S[bh, i, j] = (q_i . k_j + relbias(i,j)) / sqrt(D) - 0.1*|i-j|
// NT GEMM: A = Q rows (stride 768), B = K rows (stride 768), K=192.
// grid (8, 8, 64)
// ============================================================
__global__ __launch_bounds__(256) void gemm_scores_kernel()
{
    __shared__ float As[BM][BK + 1];
    __shared__ float Bs[BN][BK + 1];

    const int bh = blockIdx.z;
    const int b  = bh >> 2;
    const int h  = bh & 3;
    const float* A = g_q + (size_t)b * S_ * HID_ + h * HD_;
    const float* Bp = g_k + (size_t)b * S_ * HID_ + h * HD_;
    float* C = g_s + (size_t)bh * S_ * S_;

    const int tid = threadIdx.x;
    const int tx = tid & 15;
    const int ty = tid >> 4;
    const int bm = blockIdx.y * BM;
    const int bn = blockIdx.x * BN;

    float acc[4][4] = {};

    for (int k0 = 0; k0 < HD_; k0 += BK) {
        {
            int m = tid >> 2;
            int k = (tid & 3) << 2;
            float4 a4 = *(const float4*)(A + (size_t)(bm + m) * HID_ + k0 + k);
            As[m][k + 0] = a4.x; As[m][k + 1] = a4.y;
            As[m][k + 2] = a4.z; As[m][k + 3] = a4.w;
        }
        {
            int n = tid >> 2;
            int k = (tid & 3) << 2;
            float4 b4 = *(const float4*)(Bp + (size_t)(bn + n) * HID_ + k0 + k);
            Bs[n][k + 0] = b4.x; Bs[n][k + 1] = b4.y;
            Bs[n][k + 2] = b4.z; Bs[n][k + 3] = b4.w;
        }
        __syncthreads();

        #pragma unroll
        for (int kk = 0; kk < BK; ++kk) {
            float a[4], bb[4];
            #pragma unroll
            for (int i = 0; i < 4; i++) a[i] = As[ty * 4 + i][kk];
            #pragma unroll
            for (int j = 0; j < 4; j++) bb[j] = Bs[tx * 4 + j][kk];
            #pragma unroll
            for (int i = 0; i < 4; i++)
                #pragma unroll
                for (int j = 0; j < 4; j++)
                    acc[i][j] = fmaf(a[i], bb[j], acc[i][j]);
        }
        __syncthreads();
    }

    #pragma unroll
    for (int i = 0; i < 4; i++) {
        int gi = bm + ty * 4 + i;
        #pragma unroll
        for (int j = 0; j < 4; j++) {
            int gj = bn + tx * 4 + j;
            float dist = fabsf((float)(gi - gj));
            float relb = expf(-0.1f * fminf(dist, 5.0f));
            float v = (acc[i][j] + relb) * INV_SQRT_D - 0.1f * dist;
            C[(size_t)gi * S_ + gj] = v;
        }
    }
}

// ============================================================
// Softmax over rows of 512. grid = BH_*S_ blocks, 256 threads.
// ============================================================
__global__ __launch_bounds__(256) void softmax_kernel()
{
    __shared__ float red[256];
    const int row = blockIdx.x;
    float* p = g_s + (size_t)row * S_;
    const int tid = threadIdx.x;

    float v0 = p[tid];
    float v1 = p[tid + 256];
    float mx = fmaxf(v0, v1);
    red[tid] = mx;
    __syncthreads();
    for (int off = 128; off > 0; off >>= 1) {
        if (tid < off) red[tid] = fmaxf(red[tid], red[tid + off]);
        __syncthreads();
    }
    mx = red[0];
    __syncthreads();

    float e0 = expf(v0 - mx);
    float e1 = expf(v1 - mx);
    red[tid] = e0 + e1;
    __syncthreads();
    for (int off = 128; off > 0; off >>= 1) {
        if (tid < off) red[tid] += red[tid + off];
        __syncthreads();
    }
    float inv = 1.0f / red[0];
    p[tid] = e0 * inv;
    p[tid + 256] = e1 * inv;
}

// ============================================================
// PV: ctx = probs @ V per (b,h). M=512, N=192, K=512. grid (3, 8, 64)
// ============================================================
__global__ __launch_bounds__(256) void gemm_pv_kernel()
{
    const int bh = blockIdx.z;
    const int b  = bh >> 2;
    const int h  = bh & 3;
    const float* A = g_s + (size_t)bh * S_ * S_;
    const float* Bp = g_v + (size_t)b * S_ * HID_ + h * HD_;
    float* C = g_c + (size_t)b * S_ * HID_ + h * HD_;

    gemm_nn_body(A, S_, Bp, HID_, nullptr, nullptr, 0, C, HID_, S_,
                 blockIdx.y * BM, blockIdx.x * BN);
}

// ============================================================
// LayerNorm rows of 768 in-place on g_h. grid 8192, 256 threads.
// ============================================================
__global__ __launch_bounds__(256) void layernorm_kernel(
    const float* __restrict__ lng, const float* __restrict__ lnb)
{
    __shared__ float sh[HID_];
    __shared__ float red[256];
    const int row = blockIdx.x;
    float* p = g_h + (size_t)row * HID_;
    const int tid = threadIdx.x;

    float s = 0.f;
    #pragma unroll
    for (int i = 0; i < 3; i++) {
        float v = p[tid + i * 256];
        sh[tid + i * 256] = v;
        s += v;
    }
    red[tid] = s;
    __syncthreads();
    for (int off = 128; off > 0; off >>= 1) {
        if (tid < off) red[tid] += red[tid + off];
        __syncthreads();
    }
    float mu = red[0] * (1.0f / HID_);
    __syncthreads();

    float sq = 0.f;
    #pragma unroll
    for (int i = 0; i < 3; i++) {
        float d = sh[tid + i * 256] - mu;
        sq += d * d;
    }
    red[tid] = sq;
    __syncthreads();
    for (int off = 128; off > 0; off >>= 1) {
        if (tid < off) red[tid] += red[tid + off];
        __syncthreads();
    }
    float rstd = rsqrtf(red[0] * (1.0f / HID_) + 1e-5f);
    __syncthreads();

    #pragma unroll
    for (int i = 0; i < 3; i++) {
        int n = tid + i * 256;
        p[n] = (sh[n] - mu) * rstd * lng[n] + lnb[n];
    }
}

// ============================================================
// Classifier + entity-bias bump. One block per (b,s), 288 threads (9 warps).
// Warp w computes label w's logit for the current row AND the previous row
// (prev recomputed cheaply so no extra pass); thread 0 applies the bump.
// ============================================================
__global__ __launch_bounds__(288) void classifier_kernel(
    const float* __restrict__ Ws, const float* __restrict__ bs,
    const float* __restrict__ eb, float* __restrict__ out)
{
    __shared__ float cur[HID_];
    __shared__ float prv[HID_];
    __shared__ float lcur[NL_];
    __shared__ float lprv[NL_];

    const int row = blockIdx.x;
    const int s = row & (S_ - 1);
    const bool has_prev = (s > 0);
    const int tid = threadIdx.x;

    for (int i = tid; i < HID_; i += 288) cur[i] = g_h[(size_t)row * HID_ + i];
    if (has_prev)
        for (int i = tid; i < HID_; i += 288) prv[i] = g_h[(size_t)(row - 1) * HID_ + i];
    __syncthreads();

    const int w = tid >> 5;     // 0..8 = label
    const int lane = tid & 31;

    float a = 0.f, ap = 0.f;
    for (int d = lane; d < HID_; d += 32) {
        float wv = Ws[d * NL_ + w];
        a = fmaf(cur[d], wv, a);
        if (has_prev) ap = fmaf(prv[d], wv, ap);
    }
    #pragma unroll
    for (int off = 16; off > 0; off >>= 1) {
        a  += __shfl_down_sync(0xffffffffu, a, off);
        ap += __shfl_down_sync(0xffffffffu, ap, off);
    }
    if (lane == 0) {
        lcur[w] = a + bs[w];
        lprv[w] = ap + bs[w];
    }
    __syncthreads();

    if (tid == 0 && has_prev) {
        int am = 0;
        float best = lprv[0];
        #pragma unroll
        for (int l = 1; l < NL_; l++) {
            if (lprv[l] > best) { best = lprv[l]; am = l; }
        }
        if (am == 1) lcur[2] += 2.0f * eb[2];   // B_PERSON -> bump I_PERSON
    }
    __syncthreads();

    if (tid < NL_) out[(size_t)row * NL_ + tid] = lcur[tid];
}

// ============================================================
// Launch
// ============================================================
extern "C" void kernel_launch(void* const* d_in, const int* in_sizes, int n_in,
                              void* d_out, int out_size)
{
    const float* x   = (const float*)d_in[0];
    const float* Wq  = (const float*)d_in[1];
    const float* bq  = (const float*)d_in[2];
    const float* Wk  = (const float*)d_in[3];
    const float* bk  = (const float*)d_in[4];
    const float* Wv  = (const float*)d_in[5];
    const float* bv  = (const float*)d_in[6];
    const float* Wo  = (const float*)d_in[7];
    const float* bo  = (const float*)d_in[8];
    const float* lng = (const float*)d_in[9];
    const float* lnb = (const float*)d_in[10];
    const float* Ws  = (const float*)d_in[11];
    const float* bs  = (const float*)d_in[12];
    const float* eb  = (const float*)d_in[13];
    float* out = (float*)d_out;

    float *gq, *gk, *gv, *gc, *gh;
    cudaGetSymbolAddress((void**)&gq, g_q);
    cudaGetSymbolAddress((void**)&gk, g_k);
    cudaGetSymbolAddress((void**)&gv, g_v);
    cudaGetSymbolAddress((void**)&gc, g_c);
    cudaGetSymbolAddress((void**)&gh, g_h);

    dim3 gridProj(HID_ / BN, M_ROWS / BM);   // (12, 128)

    // Q, K, V projections
    gemm_nn_kernel<<<gridProj, 256>>>(x, HID_, Wq, HID_, bq, nullptr, 0, gq, HID_, HID_);
    gemm_nn_kernel<<<gridProj, 256>>>(x, HID_, Wk, HID_, bk, nullptr, 0, gk, HID_, HID_);
    gemm_nn_kernel<<<gridProj, 256>>>(x, HID_, Wv, HID_, bv, nullptr, 0, gv, HID_, HID_);

    // attention scores + bias
    gemm_scores_kernel<<<dim3(S_ / BN, S_ / BM, BH_), 256>>>();

    // softmax
    softmax_kernel<<<BH_ * S_, 256>>>();

    // probs @ V
    gemm_pv_kernel<<<dim3(HD_ / BN, S_ / BM, BH_), 256>>>();

    // output projection + residual (into g_h)
    gemm_nn_kernel<<<gridProj, 256>>>(gc, HID_, Wo, HID_, bo, x, HID_, gh, HID_, HID_);

    // layernorm
    layernorm_kernel<<<M_ROWS, 256>>>(lng, lnb);

    // classifier + entity bump
    classifier_kernel<<<M_ROWS, 288>>>(Ws, bs, eb, out);
}

// round 2
// speedup vs baseline: 1.3165x; 1.3165x over previous
#include <cuda_runtime.h>
#include <cuda_bf16.h>
#include <math.h>

// Problem constants
#define B_  16
#define S_  512
#define HID_ 768
#define NH_ 4
#define HD_ 192          // head dim
#define NL_ 9            // labels
#define M_ROWS (B_ * S_) // 8192
#define BH_ (B_ * NH_)   // 64
#define INV_SQRT_D 0.07216878364870323f  // 1/sqrt(192)

// -------- device scratch (static; no allocations allowed) --------
__device__ float g_q[M_ROWS * HID_];
__device__ float g_k[M_ROWS * HID_];
__device__ float g_v[M_ROWS * HID_];
__device__ float g_s[(size_t)BH_ * S_ * S_];   // 64 MB attention scores/probs
__device__ float g_c[M_ROWS * HID_];           // context
__device__ float g_h[M_ROWS * HID_];           // residual + LN output

// ============================================================
// 128x{128,64}x8 double-buffered SGEMM, 256 threads, 8xTN per thread.
// A row-major [M,K] (lda), B row-major [K,N] (ldb). M%128==0, K%8==0.
// ============================================================
template<int BN, int TN>
__global__ __launch_bounds__(256, 2) void sgemm_nn(
    const float* __restrict__ A, int lda,
    const float* __restrict__ B, int ldb,
    const float* __restrict__ bias,
    const float* __restrict__ resid, int ldr,
    float* __restrict__ C, int ldc, int K)
{
    __shared__ float As[2][8][128];
    __shared__ float Bs[2][8][BN];

    const int tid = threadIdx.x;
    const int bm = blockIdx.y * 128;
    const int bn = blockIdx.x * BN;
    const int tx = tid & 15;
    const int ty = tid >> 4;

    // A tile loader: 128 rows x 8 k, 4 contiguous k per thread
    const int ar = tid >> 1;
    const int ak = (tid & 1) << 2;
    const float* Aptr = A + (size_t)(bm + ar) * lda + ak;

    // B tile loader: 8 k-rows x BN cols
    const int bkr = tid >> 5;
    const int bnn = (BN == 128) ? ((tid & 31) << 2) : ((tid & 31) << 1);
    const float* Bptr = B + (size_t)bkr * ldb + bn + bnn;

    float acc[8][TN];
    #pragma unroll
    for (int i = 0; i < 8; i++)
        #pragma unroll
        for (int j = 0; j < TN; j++) acc[i][j] = 0.f;

    // prologue: load tile 0
    float4 pa = *(const float4*)Aptr;
    float4 pb4;
    float2 pb2;
    if (BN == 128) pb4 = *(const float4*)Bptr;
    else           pb2 = *(const float2*)Bptr;

    As[0][ak + 0][ar] = pa.x; As[0][ak + 1][ar] = pa.y;
    As[0][ak + 2][ar] = pa.z; As[0][ak + 3][ar] = pa.w;
    if (BN == 128) *(float4*)&Bs[0][bkr][bnn] = pb4;
    else           *(float2*)&Bs[0][bkr][bnn] = pb2;
    __syncthreads();

    const int nk = K >> 3;
    int buf = 0;
    for (int t = 0; t < nk; ++t) {
        if (t + 1 < nk) {
            pa = *(const float4*)(Aptr + (t + 1) * 8);
            if (BN == 128) pb4 = *(const float4*)(Bptr + (size_t)(t + 1) * 8 * ldb);
            else           pb2 = *(const float2*)(Bptr + (size_t)(t + 1) * 8 * ldb);
        }
        #pragma unroll
        for (int kk = 0; kk < 8; ++kk) {
            float a[8], b[TN];
            *(float4*)&a[0] = *(const float4*)&As[buf][kk][ty * 4];
            *(float4*)&a[4] = *(const float4*)&As[buf][kk][64 + ty * 4];
            *(float4*)&b[0] = *(const float4*)&Bs[buf][kk][tx * 4];
            if (TN == 8) *(float4*)&b[4] = *(const float4*)&Bs[buf][kk][64 + tx * 4];
            #pragma unroll
            for (int i = 0; i < 8; i++)
                #pragma unroll
                for (int j = 0; j < TN; j++)
                    acc[i][j] = fmaf(a[i], b[j], acc[i][j]);
        }
        if (t + 1 < nk) {
            int nb = buf ^ 1;
            As[nb][ak + 0][ar] = pa.x; As[nb][ak + 1][ar] = pa.y;
            As[nb][ak + 2][ar] = pa.z; As[nb][ak + 3][ar] = pa.w;
            if (BN == 128) *(float4*)&Bs[nb][bkr][bnn] = pb4;
            else           *(float2*)&Bs[nb][bkr][bnn] = pb2;
            __syncthreads();
            buf = nb;
        }
    }

    #pragma unroll
    for (int i = 0; i < 8; i++) {
        int m = bm + ((i < 4) ? ty * 4 + i : 64 + ty * 4 + (i - 4));
        #pragma unroll
        for (int j = 0; j < TN; j++) {
            int n = bn + ((TN == 8) ? ((j < 4) ? tx * 4 + j : 64 + tx * 4 + (j - 4))
                                    : tx * 4 + j);
            float v = acc[i][j];
            if (bias)  v += bias[n];
            if (resid) v += resid[(size_t)m * ldr + n];
            C[(size_t)m * ldc + n] = v;
        }
    }
}

// ============================================================
// Scores: 128x128x8 NT SGEMM + bias epilogue.
// S[bh,i,j] = (q_i.k_j + exp(-0.1*min(|i-j|,5))) / sqrt(D) - 0.1*|i-j|
// grid (4, 4, 64)
// ============================================================
__global__ __launch_bounds__(256, 2) void sgemm_scores()
{
    __shared__ float As[2][8][128];
    __shared__ float Bs[2][8][128];

    const int tid = threadIdx.x;
    const int bh = blockIdx.z;
    const int b  = bh >> 2;
    const int h  = bh & 3;
    const float* A  = g_q + (size_t)b * S_ * HID_ + h * HD_;
    const float* Bp = g_k + (size_t)b * S_ * HID_ + h * HD_;
    float* C = g_s + (size_t)bh * S_ * S_;

    const int bm = blockIdx.y * 128;
    const int bn = blockIdx.x * 128;
    const int tx = tid & 15;
    const int ty = tid >> 4;

    const int ar = tid >> 1;
    const int ak = (tid & 1) << 2;
    const float* Aptr = A  + (size_t)(bm + ar) * HID_ + ak;
    const float* Bptr = Bp + (size_t)(bn + ar) * HID_ + ak;  // NT: rows are n

    float acc[8][8];
    #pragma unroll
    for (int i = 0; i < 8; i++)
        #pragma unroll
        for (int j = 0; j < 8; j++) acc[i][j] = 0.f;

    float4 pa = *(const float4*)Aptr;
    float4 pb = *(const float4*)Bptr;
    As[0][ak + 0][ar] = pa.x; As[0][ak + 1][ar] = pa.y;
    As[0][ak + 2][ar] = pa.z; As[0][ak + 3][ar] = pa.w;
    Bs[0][ak + 0][ar] = pb.x; Bs[0][ak + 1][ar] = pb.y;
    Bs[0][ak + 2][ar] = pb.z; Bs[0][ak + 3][ar] = pb.w;
    __syncthreads();

    const int nk = HD_ >> 3;  // 24
    int buf = 0;
    for (int t = 0; t < nk; ++t) {
        if (t + 1 < nk) {
            pa = *(const float4*)(Aptr + (t + 1) * 8);
            pb = *(const float4*)(Bptr + (t + 1) * 8);
        }
        #pragma unroll
        for (int kk = 0; kk < 8; ++kk) {
            float a[8], bb[8];
            *(float4*)&a[0]  = *(const float4*)&As[buf][kk][ty * 4];
            *(float4*)&a[4]  = *(const float4*)&As[buf][kk][64 + ty * 4];
            *(float4*)&bb[0] = *(const float4*)&Bs[buf][kk][tx * 4];
            *(float4*)&bb[4] = *(const float4*)&Bs[buf][kk][64 + tx * 4];
            #pragma unroll
            for (int i = 0; i < 8; i++)
                #pragma unroll
                for (int j = 0; j < 8; j++)
                    acc[i][j] = fmaf(a[i], bb[j], acc[i][j]);
        }
        if (t + 1 < nk) {
            int nb = buf ^ 1;
            As[nb][ak + 0][ar] = pa.x; As[nb][ak + 1][ar] = pa.y;
            As[nb][ak + 2][ar] = pa.z; As[nb][ak + 3][ar] = pa.w;
            Bs[nb][ak + 0][ar] = pb.x; Bs[nb][ak + 1][ar] = pb.y;
            Bs[nb][ak + 2][ar] = pb.z; Bs[nb][ak + 3][ar] = pb.w;
            __syncthreads();
            buf = nb;
        }
    }

    #pragma unroll
    for (int i = 0; i < 8; i++) {
        int gi = bm + ((i < 4) ? ty * 4 + i : 64 + ty * 4 + (i - 4));
        #pragma unroll
        for (int j = 0; j < 8; j++) {
            int gj = bn + ((j < 4) ? tx * 4 + j : 64 + tx * 4 + (j - 4));
            float dist = fabsf((float)(gi - gj));
            float relb = __expf(-0.1f * fminf(dist, 5.0f));
            C[(size_t)gi * S_ + gj] = (acc[i][j] + relb) * INV_SQRT_D - 0.1f * dist;
        }
    }
}

// ============================================================
// Softmax over rows of 512. grid = BH_*S_ blocks, 256 threads.
// ============================================================
__global__ __launch_bounds__(256) void softmax_kernel()
{
    __shared__ float red[256];
    const int row = blockIdx.x;
    float* p = g_s + (size_t)row * S_;
    const int tid = threadIdx.x;

    float v0 = p[tid];
    float v1 = p[tid + 256];
    float mx = fmaxf(v0, v1);
    red[tid] = mx;
    __syncthreads();
    for (int off = 128; off > 0; off >>= 1) {
        if (tid < off) red[tid] = fmaxf(red[tid], red[tid + off]);
        __syncthreads();
    }
    mx = red[0];
    __syncthreads();

    float e0 = __expf(v0 - mx);
    float e1 = __expf(v1 - mx);
    red[tid] = e0 + e1;
    __syncthreads();
    for (int off = 128; off > 0; off >>= 1) {
        if (tid < off) red[tid] += red[tid + off];
        __syncthreads();
    }
    float inv = 1.0f / red[0];
    p[tid] = e0 * inv;
    p[tid + 256] = e1 * inv;
}

// ============================================================
// LayerNorm rows of 768 in-place on g_h. grid 8192, 256 threads.
// ============================================================
__global__ __launch_bounds__(256) void layernorm_kernel(
    const float* __restrict__ lng, const float* __restrict__ lnb)
{
    __shared__ float sh[HID_];
    __shared__ float red[256];
    const int row = blockIdx.x;
    float* p = g_h + (size_t)row * HID_;
    const int tid = threadIdx.x;

    float s = 0.f;
    #pragma unroll
    for (int i = 0; i < 3; i++) {
        float v = p[tid + i * 256];
        sh[tid + i * 256] = v;
        s += v;
    }
    red[tid] = s;
    __syncthreads();
    for (int off = 128; off > 0; off >>= 1) {
        if (tid < off) red[tid] += red[tid + off];
        __syncthreads();
    }
    float mu = red[0] * (1.0f / HID_);
    __syncthreads();

    float sq = 0.f;
    #pragma unroll
    for (int i = 0; i < 3; i++) {
        float d = sh[tid + i * 256] - mu;
        sq += d * d;
    }
    red[tid] = sq;
    __syncthreads();
    for (int off = 128; off > 0; off >>= 1) {
        if (tid < off) red[tid] += red[tid + off];
        __syncthreads();
    }
    float rstd = rsqrtf(red[0] * (1.0f / HID_) + 1e-5f);
    __syncthreads();

    #pragma unroll
    for (int i = 0; i < 3; i++) {
        int n = tid + i * 256;
        p[n] = (sh[n] - mu) * rstd * lng[n] + lnb[n];
    }
}

// ============================================================
// Classifier + entity-bias bump. One block per (b,s), 288 threads (9 warps).
// ============================================================
__global__ __launch_bounds__(288) void classifier_kernel(
    const float* __restrict__ Ws, const float* __restrict__ bs,
    const float* __restrict__ eb, float* __restrict__ out)
{
    __shared__ float cur[HID_];
    __shared__ float prv[HID_];
    __shared__ float lcur[NL_];
    __shared__ float lprv[NL_];

    const int row = blockIdx.x;
    const int s = row & (S_ - 1);
    const bool has_prev = (s > 0);
    const int tid = threadIdx.x;

    for (int i = tid; i < HID_; i += 288) cur[i] = g_h[(size_t)row * HID_ + i];
    if (has_prev)
        for (int i = tid; i < HID_; i += 288) prv[i] = g_h[(size_t)(row - 1) * HID_ + i];
    __syncthreads();

    const int w = tid >> 5;
    const int lane = tid & 31;

    float a = 0.f, ap = 0.f;
    for (int d = lane; d < HID_; d += 32) {
        float wv = Ws[d * NL_ + w];
        a = fmaf(cur[d], wv, a);
        if (has_prev) ap = fmaf(prv[d], wv, ap);
    }
    #pragma unroll
    for (int off = 16; off > 0; off >>= 1) {
        a  += __shfl_down_sync(0xffffffffu, a, off);
        ap += __shfl_down_sync(0xffffffffu, ap, off);
    }
    if (lane == 0) {
        lcur[w] = a + bs[w];
        lprv[w] = ap + bs[w];
    }
    __syncthreads();

    if (tid == 0 && has_prev) {
        int am = 0;
        float best = lprv[0];
        #pragma unroll
        for (int l = 1; l < NL_; l++) {
            if (lprv[l] > best) { best = lprv[l]; am = l; }
        }
        if (am == 1) lcur[2] += 2.0f * eb[2];
    }
    __syncthreads();

    if (tid < NL_) out[(size_t)row * NL_ + tid] = lcur[tid];
}

// ============================================================
// Launch
// ============================================================
extern "C" void kernel_launch(void* const* d_in, const int* in_sizes, int n_in,
                              void* d_out, int out_size)
{
    const float* x   = (const float*)d_in[0];
    const float* Wq  = (const float*)d_in[1];
    const float* bq  = (const float*)d_in[2];
    const float* Wk  = (const float*)d_in[3];
    const float* bk  = (const float*)d_in[4];
    const float* Wv  = (const float*)d_in[5];
    const float* bv  = (const float*)d_in[6];
    const float* Wo  = (const float*)d_in[7];
    const float* bo  = (const float*)d_in[8];
    const float* lng = (const float*)d_in[9];
    const float* lnb = (const float*)d_in[10];
    const float* Ws  = (const float*)d_in[11];
    const float* bs  = (const float*)d_in[12];
    const float* eb  = (const float*)d_in[13];
    float* out = (float*)d_out;

    float *gq, *gk, *gv, *gs, *gc, *gh;
    cudaGetSymbolAddress((void**)&gq, g_q);
    cudaGetSymbolAddress((void**)&gk, g_k);
    cudaGetSymbolAddress((void**)&gv, g_v);
    cudaGetSymbolAddress((void**)&gs, g_s);
    cudaGetSymbolAddress((void**)&gc, g_c);
    cudaGetSymbolAddress((void**)&gh, g_h);

    dim3 gridProj(HID_ / 128, M_ROWS / 128);   // (6, 64)

    // Q, K, V projections
    sgemm_nn<128, 8><<<gridProj, 256>>>(x, HID_, Wq, HID_, bq, nullptr, 0, gq, HID_, HID_);
    sgemm_nn<128, 8><<<gridProj, 256>>>(x, HID_, Wk, HID_, bk, nullptr, 0, gk, HID_, HID_);
    sgemm_nn<128, 8><<<gridProj, 256>>>(x, HID_, Wv, HID_, bv, nullptr, 0, gv, HID_, HID_);

    // attention scores + bias: grid (4,4,64)
    sgemm_scores<<<dim3(S_ / 128, S_ / 128, BH_), 256>>>();

    // softmax
    softmax_kernel<<<BH_ * S_, 256>>>();

    // probs @ V per (b,h): M=512, N=192 (BN=64 -> grid (3,4,64))
    {
        dim3 g(HD_ / 64, S_ / 128, BH_);
        for (int z = 0; z < 1; ++z) {} // no-op
        // per-bh pointers handled via blockIdx.z inside a wrapper: use a small
        // launcher kernel approach instead: reuse sgemm_nn per bh is too many
        // launches; instead launch one grid with z and compute pointers in a
        // dedicated kernel below.
    }
    // PV via dedicated kernel (pointer arithmetic on blockIdx.z)
    extern __global__ void sgemm_pv();
    sgemm_pv<<<dim3(HD_ / 64, S_ / 128, BH_), 256>>>();

    // output projection + residual (into g_h)
    sgemm_nn<128, 8><<<gridProj, 256>>>(gc, HID_, Wo, HID_, bo, x, HID_, gh, HID_, HID_);

    // layernorm
    layernorm_kernel<<<M_ROWS, 256>>>(lng, lnb);

    // classifier + entity bump
    classifier_kernel<<<M_ROWS, 288>>>(Ws, bs, eb, out);
}

// ============================================================
// PV: ctx = probs @ V per (b,h). 128x64x8 tiles. grid (3, 4, 64)
// ============================================================
__global__ __launch_bounds__(256, 2) void sgemm_pv()
{
    __shared__ float As[2][8][128];
    __shared__ float Bs[2][8][64];

    const int tid = threadIdx.x;
    const int bh = blockIdx.z;
    const int b  = bh >> 2;
    const int h  = bh & 3;
    const float* A  = g_s + (size_t)bh * S_ * S_;
    const float* Bp = g_v + (size_t)b * S_ * HID_ + h * HD_;
    float* C = g_c + (size_t)b * S_ * HID_ + h * HD_;

    const int bm = blockIdx.y * 128;
    const int bn = blockIdx.x * 64;
    const int tx = tid & 15;
    const int ty = tid >> 4;

    const int ar = tid >> 1;
    const int ak = (tid & 1) << 2;
    const float* Aptr = A + (size_t)(bm + ar) * S_ + ak;

    const int bkr = tid >> 5;
    const int bnn = (tid & 31) << 1;
    const float* Bptr = Bp + (size_t)bkr * HID_ + bn + bnn;

    float acc[8][4];
    #pragma unroll
    for (int i = 0; i < 8; i++)
        #pragma unroll
        for (int j = 0; j < 4; j++) acc[i][j] = 0.f;

    float4 pa = *(const float4*)Aptr;
    float2 pb = *(const float2*)Bptr;
    As[0][ak + 0][ar] = pa.x; As[0][ak + 1][ar] = pa.y;
    As[0][ak + 2][ar] = pa.z; As[0][ak + 3][ar] = pa.w;
    *(float2*)&Bs[0][bkr][bnn] = pb;
    __syncthreads();

    const int nk = S_ >> 3;  // 64
    int buf = 0;
    for (int t = 0; t < nk; ++t) {
        if (t + 1 < nk) {
            pa = *(const float4*)(Aptr + (t + 1) * 8);
            pb = *(const float2*)(Bptr + (size_t)(t + 1) * 8 * HID_);
        }
        #pragma unroll
        for (int kk = 0; kk < 8; ++kk) {
            float a[8], bb[4];
            *(float4*)&a[0]  = *(const float4*)&As[buf][kk][ty * 4];
            *(float4*)&a[4]  = *(const float4*)&As[buf][kk][64 + ty * 4];
            *(float4*)&bb[0] = *(const float4*)&Bs[buf][kk][tx * 4];
            #pragma unroll
            for (int i = 0; i < 8; i++)
                #pragma unroll
                for (int j = 0; j < 4; j++)
                    acc[i][j] = fmaf(a[i], bb[j], acc[i][j]);
        }
        if (t + 1 < nk) {
            int nb = buf ^ 1;
            As[nb][ak + 0][ar] = pa.x; As[nb][ak + 1][ar] = pa.y;
            As[nb][ak + 2][ar] = pa.z; As[nb][ak + 3][ar] = pa.w;
            *(float2*)&Bs[nb][bkr][bnn] = pb;
            __syncthreads();
            buf = nb;
        }
    }

    #pragma unroll
    for (int i = 0; i < 8; i++) {
        int m = bm + ((i < 4) ? ty * 4 + i : 64 + ty * 4 + (i - 4));
        #pragma unroll
        for (int j = 0; j < 4; j++) {
            int n = bn + tx * 4 + j;
            C[(size_t)m * HID_ + n] = acc[i][j];
        }
    }
}

// round 4
// speedup vs baseline: 1.4195x; 1.0782x over previous
#include <cuda_runtime.h>
#include <cuda_bf16.h>
#include <cstdint>
#include <math.h>

// ---------------- problem constants ----------------
#define B_   16
#define S_   512
#define HID_ 768
#define NH_  4
#define HD_  192
#define NL_  9
#define M_ROWS (B_ * S_)   // 8192
#define BH_ (B_ * NH_)     // 64
#define INV_SQRT_D 0.07216878364870323f

// ---------------- mma helpers (sm_80-compatible PTX only) ----------------
__device__ __forceinline__ uint32_t smem_to_u32(const void* p) {
    uint32_t a;
    asm("{ .reg .u64 t; cvta.to.shared.u64 t, %1; cvt.u32.u64 %0, t; }" : "=r"(a) : "l"(p));
    return a;
}
__device__ __forceinline__ void ldsm_x4(uint32_t* r, uint32_t addr) {
    asm volatile("ldmatrix.sync.aligned.m8n8.x4.shared.b16 {%0,%1,%2,%3}, [%4];"
        : "=r"(r[0]), "=r"(r[1]), "=r"(r[2]), "=r"(r[3]) : "r"(addr));
}
__device__ __forceinline__ void mma16816(float* d, const uint32_t* a, const uint32_t* b) {
    asm volatile("mma.sync.aligned.m16n8k16.row.col.f32.bf16.bf16.f32 "
        "{%0,%1,%2,%3}, {%4,%5,%6,%7}, {%8,%9}, {%0,%1,%2,%3};"
        : "+f"(d[0]), "+f"(d[1]), "+f"(d[2]), "+f"(d[3])
        : "r"(a[0]), "r"(a[1]), "r"(a[2]), "r"(a[3]), "r"(b[0]), "r"(b[1]));
}

// ---------------- device scratch ----------------
__device__ __nv_bfloat16 g_xhi[M_ROWS * HID_],  g_xlo[M_ROWS * HID_];
__device__ __nv_bfloat16 g_wqkvThi[3 * HID_ * HID_], g_wqkvTlo[3 * HID_ * HID_];
__device__ __nv_bfloat16 g_woThi[HID_ * HID_],  g_woTlo[HID_ * HID_];
__device__ float         g_qkv[(size_t)M_ROWS * 3 * HID_];
__device__ __nv_bfloat16 g_qhi[M_ROWS * HID_], g_qlo[M_ROWS * HID_];
__device__ __nv_bfloat16 g_khi[M_ROWS * HID_], g_klo[M_ROWS * HID_];
__device__ __nv_bfloat16 g_vThi[(size_t)BH_ * HD_ * S_], g_vTlo[(size_t)BH_ * HD_ * S_];
__device__ float         g_s[(size_t)BH_ * S_ * S_];
__device__ __nv_bfloat16 g_phi[(size_t)BH_ * S_ * S_], g_plo[(size_t)BH_ * S_ * S_];
__device__ float         g_c[M_ROWS * HID_];
__device__ float         g_h[M_ROWS * HID_];

__device__ __forceinline__ void split_bf(float v, __nv_bfloat16& hi, __nv_bfloat16& lo) {
    hi = __float2bfloat16(v);
    lo = __float2bfloat16(v - __bfloat162float(hi));
}

// ---------------- conversion kernels ----------------
__global__ __launch_bounds__(256) void split4_kernel(
    const float* __restrict__ src, __nv_bfloat16* __restrict__ hi,
    __nv_bfloat16* __restrict__ lo, int n4)
{
    int i = blockIdx.x * 256 + threadIdx.x;
    if (i >= n4) return;
    float4 v = ((const float4*)src)[i];
    __nv_bfloat16 h, l;
    split_bf(v.x, h, l); hi[i*4+0] = h; lo[i*4+0] = l;
    split_bf(v.y, h, l); hi[i*4+1] = h; lo[i*4+1] = l;
    split_bf(v.z, h, l); hi[i*4+2] = h; lo[i*4+2] = l;
    split_bf(v.w, h, l); hi[i*4+3] = h; lo[i*4+3] = l;
}

__global__ __launch_bounds__(256) void split_qk_kernel()
{
    int i = blockIdx.x * 256 + threadIdx.x;   // per float4 of [8192,768]
    int row = i / 192;
    int c4  = i - row * 192;
    float4 q = *(const float4*)(g_qkv + (size_t)row * 2304 + c4 * 4);
    float4 k = *(const float4*)(g_qkv + (size_t)row * 2304 + 768 + c4 * 4);
    size_t o = (size_t)row * 768 + c4 * 4;
    __nv_bfloat16 h, l;
    split_bf(q.x, h, l); g_qhi[o+0] = h; g_qlo[o+0] = l;
    split_bf(q.y, h, l); g_qhi[o+1] = h; g_qlo[o+1] = l;
    split_bf(q.z, h, l); g_qhi[o+2] = h; g_qlo[o+2] = l;
    split_bf(q.w, h, l); g_qhi[o+3] = h; g_qlo[o+3] = l;
    split_bf(k.x, h, l); g_khi[o+0] = h; g_klo[o+0] = l;
    split_bf(k.y, h, l); g_khi[o+1] = h; g_klo[o+1] = l;
    split_bf(k.z, h, l); g_khi[o+2] = h; g_klo[o+2] = l;
    split_bf(k.w, h, l); g_khi[o+3] = h; g_klo[o+3] = l;
}

// weight transpose + split: z in {0,1,2}->qkvT combined, 3->woT
__global__ void wtrans_kernel(const float* __restrict__ Wq, const float* __restrict__ Wk,
                              const float* __restrict__ Wv, const float* __restrict__ Wo)
{
    __shared__ float tl[32][33];
    const int z = blockIdx.z;
    const float* W = (z == 0) ? Wq : (z == 1) ? Wk : (z == 2) ? Wv : Wo;
    const int n0 = blockIdx.x * 32, k0 = blockIdx.y * 32;
    const int tx = threadIdx.x, ty = threadIdx.y;  // (32,8)
    #pragma unroll
    for (int i = 0; i < 4; i++) {
        int k = ty + i * 8;
        tl[k][tx] = W[(size_t)(k0 + k) * HID_ + n0 + tx];
    }
    __syncthreads();
    #pragma unroll
    for (int i = 0; i < 4; i++) {
        int nloc = ty + i * 8;
        float v = tl[tx][nloc];
        __nv_bfloat16 h, l; split_bf(v, h, l);
        if (z < 3) {
            size_t o = (size_t)(z * HID_ + n0 + nloc) * HID_ + k0 + tx;
            g_wqkvThi[o] = h; g_wqkvTlo[o] = l;
        } else {
            size_t o = (size_t)(n0 + nloc) * HID_ + k0 + tx;
            g_woThi[o] = h; g_woTlo[o] = l;
        }
    }
}

// v transpose + split: vT[bh][d][s]
__global__ void vtrans_kernel()
{
    __shared__ float tl[32][33];
    const int bh = blockIdx.z, b = bh >> 2, h = bh & 3;
    const int s0 = blockIdx.x * 32, d0 = blockIdx.y * 32;
    const int tx = threadIdx.x, ty = threadIdx.y;  // (32,8)
    #pragma unroll
    for (int i = 0; i < 4; i++) {
        int s = s0 + ty + i * 8;
        tl[ty + i * 8][tx] = g_qkv[(size_t)(b * S_ + s) * 2304 + 1536 + h * HD_ + d0 + tx];
    }
    __syncthreads();
    #pragma unroll
    for (int i = 0; i < 4; i++) {
        int d = d0 + ty + i * 8;
        float v = tl[tx][ty + i * 8];
        __nv_bfloat16 hh, ll; split_bf(v, hh, ll);
        size_t o = ((size_t)bh * HD_ + d) * S_ + s0 + tx;
        g_vThi[o] = hh; g_vTlo[o] = ll;
    }
}

// ---------------- split-bf16 mma.sync GEMM ----------------
// NT form: C[m,n] = sum_k (Ahi+Alo)[m,k]*(Bhi+Blo)[n,k]  (3 mma products)
// Block 128 x NTILE, 8 warps 2x4, warp tile 64 x (NTILE/4), k-chunk 32.
// MODE 0: QKV proj (bias over 3 segments)  1: O proj (bias + residual)
// MODE 2: scores (rel-bias epilogue, batched over bh)  3: PV (batched over bh)
template<int MODE>
__device__ __forceinline__ float epi_apply(float v, int gm, int n,
    const float* bb0, const float* bb1, const float* bb2, const float* resid)
{
    if (MODE == 0) {
        v += (n < 768) ? bb0[n] : (n < 1536) ? bb1[n - 768] : bb2[n - 1536];
    } else if (MODE == 1) {
        v += bb0[n] + resid[(size_t)gm * HID_ + n];
    } else if (MODE == 2) {
        float dist = fabsf((float)(gm - n));
        float relb = __expf(-0.1f * fminf(dist, 5.0f));
        v = (v + relb) * INV_SQRT_D - 0.1f * dist;
    }
    return v;
}

template<int MODE, int NTILE>
__global__ __launch_bounds__(256) void mma_gemm(
    const __nv_bfloat16* __restrict__ Ahi, const __nv_bfloat16* __restrict__ Alo, int lda,
    const __nv_bfloat16* __restrict__ Bhi, const __nv_bfloat16* __restrict__ Blo, int ldb,
    float* __restrict__ C, int ldc, int K,
    const float* __restrict__ bb0, const float* __restrict__ bb1,
    const float* __restrict__ bb2, const float* __restrict__ resid)
{
    constexpr int WN   = NTILE / 4;     // warp n extent: 32 or 16
    constexpr int NB   = WN / 16;       // B ldmatrix.x4 groups: 2 or 1
    constexpr int NT8  = WN / 8;        // n8 accum tiles per warp: 4 or 2
    constexpr int ASZ  = 128 * 40 * 2;  // bytes per A (hi or lo) stage
    constexpr int BSZ  = NTILE * 40 * 2;
    constexpr int STAGE = 2 * ASZ + 2 * BSZ;
    constexpr int BLD  = (NTILE == 128) ? 2 : 1;   // B uint4 loads per thread

    extern __shared__ char smem[];
    const uint32_t sbase = smem_to_u32(smem);
    const int tid  = threadIdx.x;
    const int lane = tid & 31;
    const int wid  = tid >> 5;
    const int wm   = (wid >> 2) * 64;
    const int wn   = (wid & 3) * WN;

    size_t aoff = 0, boff = 0, coff = 0;
    if (MODE == 2) {
        int bh = blockIdx.z, b = bh >> 2, h = bh & 3;
        aoff = (size_t)b * S_ * HID_ + h * HD_;  boff = aoff;
        coff = (size_t)bh * S_ * S_;
    } else if (MODE == 3) {
        int bh = blockIdx.z, b = bh >> 2, h = bh & 3;
        aoff = (size_t)bh * S_ * S_;
        boff = (size_t)bh * HD_ * S_;
        coff = (size_t)b * S_ * HID_ + h * HD_;
    }

    const int bm = blockIdx.y * 128;
    const int bn = blockIdx.x * NTILE;

    const __nv_bfloat16* Ah = Ahi + aoff + (size_t)bm * lda;
    const __nv_bfloat16* Al = Alo + aoff + (size_t)bm * lda;
    const __nv_bfloat16* Bh = Bhi + boff + (size_t)bn * ldb;
    const __nv_bfloat16* Bl = Blo + boff + (size_t)bn * ldb;

    // loader geometry: each thread handles uint4 (8 bf16) chunks
    const int lr = tid >> 2;              // 0..63
    const int lc = (tid & 3) * 8;         // element col within 32-k chunk

    float acc[4][NT8][4];
    #pragma unroll
    for (int i = 0; i < 4; i++)
        #pragma unroll
        for (int j = 0; j < NT8; j++)
            #pragma unroll
            for (int u = 0; u < 4; u++) acc[i][j][u] = 0.f;

    const int nt = K >> 5;   // k-chunks of 32
    uint4 rah[2], ral[2], rbh[2], rbl[2];

    // ---- prologue: load chunk 0 ----
    rah[0] = *(const uint4*)(Ah + (size_t)lr * lda + lc);
    rah[1] = *(const uint4*)(Ah + (size_t)(lr + 64) * lda + lc);
    ral[0] = *(const uint4*)(Al + (size_t)lr * lda + lc);
    ral[1] = *(const uint4*)(Al + (size_t)(lr + 64) * lda + lc);
    rbh[0] = *(const uint4*)(Bh + (size_t)lr * ldb + lc);
    rbl[0] = *(const uint4*)(Bl + (size_t)lr * ldb + lc);
    if (BLD == 2) {
        rbh[1] = *(const uint4*)(Bh + (size_t)(lr + 64) * ldb + lc);
        rbl[1] = *(const uint4*)(Bl + (size_t)(lr + 64) * ldb + lc);
    }
    {
        char* st = smem;  // buf 0
        *(uint4*)(st + lr * 80 + lc * 2) = rah[0];
        *(uint4*)(st + (lr + 64) * 80 + lc * 2) = rah[1];
        *(uint4*)(st + ASZ + lr * 80 + lc * 2) = ral[0];
        *(uint4*)(st + ASZ + (lr + 64) * 80 + lc * 2) = ral[1];
        *(uint4*)(st + 2 * ASZ + lr * 80 + lc * 2) = rbh[0];
        *(uint4*)(st + 2 * ASZ + BSZ + lr * 80 + lc * 2) = rbl[0];
        if (BLD == 2) {
            *(uint4*)(st + 2 * ASZ + (lr + 64) * 80 + lc * 2) = rbh[1];
            *(uint4*)(st + 2 * ASZ + BSZ + (lr + 64) * 80 + lc * 2) = rbl[1];
        }
    }
    __syncthreads();

    for (int t = 0; t < nt; ++t) {
        // prefetch chunk t+1 into registers
        if (t + 1 < nt) {
            const __nv_bfloat16* Ahn = Ah + (t + 1) * 32;
            const __nv_bfloat16* Aln = Al + (t + 1) * 32;
            const __nv_bfloat16* Bhn = Bh + (t + 1) * 32;
            const __nv_bfloat16* Bln = Bl + (t + 1) * 32;
            rah[0] = *(const uint4*)(Ahn + (size_t)lr * lda + lc);
            rah[1] = *(const uint4*)(Ahn + (size_t)(lr + 64) * lda + lc);
            ral[0] = *(const uint4*)(Aln + (size_t)lr * lda + lc);
            ral[1] = *(const uint4*)(Aln + (size_t)(lr + 64) * lda + lc);
            rbh[0] = *(const uint4*)(Bhn + (size_t)lr * ldb + lc);
            rbl[0] = *(const uint4*)(Bln + (size_t)lr * ldb + lc);
            if (BLD == 2) {
                rbh[1] = *(const uint4*)(Bhn + (size_t)(lr + 64) * ldb + lc);
                rbl[1] = *(const uint4*)(Bln + (size_t)(lr + 64) * ldb + lc);
            }
        }

        // compute on buffer t&1
        {
            const uint32_t aHiB = sbase + (t & 1) * STAGE;
            const uint32_t aLoB = aHiB + ASZ;
            const uint32_t bHiB = aHiB + 2 * ASZ;
            const uint32_t bLoB = bHiB + BSZ;
            #pragma unroll
            for (int ks = 0; ks < 2; ++ks) {
                const int k0 = ks * 16;
                uint32_t ah[4][4], al[4][4];
                const uint32_t arow = wm + (lane & 15);
                const uint32_t acol = k0 + ((lane >> 4) << 3);
                #pragma unroll
                for (int im = 0; im < 4; im++) {
                    uint32_t off = (arow + im * 16) * 80 + acol * 2;
                    ldsm_x4(ah[im], aHiB + off);
                    ldsm_x4(al[im], aLoB + off);
                }
                uint32_t bhf[NB][4], blf[NB][4];
                const uint32_t brow = wn + (lane & 7) + ((lane >> 4) << 3);
                const uint32_t bcol = k0 + (((lane >> 3) & 1) << 3);
                #pragma unroll
                for (int ib = 0; ib < NB; ib++) {
                    uint32_t off = (brow + ib * 16) * 80 + bcol * 2;
                    ldsm_x4(bhf[ib], bHiB + off);
                    ldsm_x4(blf[ib], bLoB + off);
                }
                #pragma unroll
                for (int im = 0; im < 4; im++)
                    #pragma unroll
                    for (int in = 0; in < NT8; in++) {
                        const uint32_t* bh2 = &bhf[in >> 1][(in & 1) * 2];
                        const uint32_t* bl2 = &blf[in >> 1][(in & 1) * 2];
                        mma16816(acc[im][in], ah[im], bh2);
                        mma16816(acc[im][in], ah[im], bl2);
                        mma16816(acc[im][in], al[im], bh2);
                    }
            }
        }

        // store chunk t+1 to the other buffer
        if (t + 1 < nt) {
            char* st = smem + ((t + 1) & 1) * STAGE;
            *(uint4*)(st + lr * 80 + lc * 2) = rah[0];
            *(uint4*)(st + (lr + 64) * 80 + lc * 2) = rah[1];
            *(uint4*)(st + ASZ + lr * 80 + lc * 2) = ral[0];
            *(uint4*)(st + ASZ + (lr + 64) * 80 + lc * 2) = ral[1];
            *(uint4*)(st + 2 * ASZ + lr * 80 + lc * 2) = rbh[0];
            *(uint4*)(st + 2 * ASZ + BSZ + lr * 80 + lc * 2) = rbl[0];
            if (BLD == 2) {
                *(uint4*)(st + 2 * ASZ + (lr + 64) * 80 + lc * 2) = rbh[1];
                *(uint4*)(st + 2 * ASZ + BSZ + (lr + 64) * 80 + lc * 2) = rbl[1];
            }
            __syncthreads();
        }
    }

    // ---- epilogue ----
    #pragma unroll
    for (int im = 0; im < 4; im++) {
        #pragma unroll
        for (int in = 0; in < NT8; in++) {
            const int gm0 = bm + wm + im * 16 + (lane >> 2);
            const int n   = bn + wn + in * 8 + ((lane & 3) << 1);
            float* d = acc[im][in];
            float2 o0, o1;
            o0.x = epi_apply<MODE>(d[0], gm0,     n,     bb0, bb1, bb2, resid);
            o0.y = epi_apply<MODE>(d[1], gm0,     n + 1, bb0, bb1, bb2, resid);
            o1.x = epi_apply<MODE>(d[2], gm0 + 8, n,     bb0, bb1, bb2, resid);
            o1.y = epi_apply<MODE>(d[3], gm0 + 8, n + 1, bb0, bb1, bb2, resid);
            *(float2*)(C + coff + (size_t)gm0 * ldc + n)       = o0;
            *(float2*)(C + coff + (size_t)(gm0 + 8) * ldc + n) = o1;
        }
    }
}

// ---------------- softmax + split ----------------
__global__ __launch_bounds__(256) void softmax_split_kernel()
{
    __shared__ float red[256];
    const int row = blockIdx.x;
    const float* p = g_s + (size_t)row * S_;
    const int tid = threadIdx.x;

    float v0 = p[tid];
    float v1 = p[tid + 256];
    float mx = fmaxf(v0, v1);
    red[tid] = mx;
    __syncthreads();
    for (int off = 128; off > 0; off >>= 1) {
        if (tid < off) red[tid] = fmaxf(red[tid], red[tid + off]);
        __syncthreads();
    }
    mx = red[0];
    __syncthreads();

    float e0 = __expf(v0 - mx);
    float e1 = __expf(v1 - mx);
    red[tid] = e0 + e1;
    __syncthreads();
    for (int off = 128; off > 0; off >>= 1) {
        if (tid < off) red[tid] += red[tid + off];
        __syncthreads();
    }
    float inv = 1.0f / red[0];
    float p0 = e0 * inv, p1 = e1 * inv;
    __nv_bfloat16 h, l;
    size_t o = (size_t)row * S_;
    split_bf(p0, h, l); g_phi[o + tid] = h;       g_plo[o + tid] = l;
    split_bf(p1, h, l); g_phi[o + tid + 256] = h; g_plo[o + tid + 256] = l;
}

// ---------------- LayerNorm ----------------
__global__ __launch_bounds__(256) void layernorm_kernel(
    const float* __restrict__ lng, const float* __restrict__ lnb)
{
    __shared__ float sh[HID_];
    __shared__ float red[256];
    const int row = blockIdx.x;
    float* p = g_h + (size_t)row * HID_;
    const int tid = threadIdx.x;

    float s = 0.f;
    #pragma unroll
    for (int i = 0; i < 3; i++) {
        float v = p[tid + i * 256];
        sh[tid + i * 256] = v;
        s += v;
    }
    red[tid] = s;
    __syncthreads();
    for (int off = 128; off > 0; off >>= 1) {
        if (tid < off) red[tid] += red[tid + off];
        __syncthreads();
    }
    float mu = red[0] * (1.0f / HID_);
    __syncthreads();

    float sq = 0.f;
    #pragma unroll
    for (int i = 0; i < 3; i++) {
        float d = sh[tid + i * 256] - mu;
        sq += d * d;
    }
    red[tid] = sq;
    __syncthreads();
    for (int off = 128; off > 0; off >>= 1) {
        if (tid < off) red[tid] += red[tid + off];
        __syncthreads();
    }
    float rstd = rsqrtf(red[0] * (1.0f / HID_) + 1e-5f);
    __syncthreads();

    #pragma unroll
    for (int i = 0; i < 3; i++) {
        int n = tid + i * 256;
        p[n] = (sh[n] - mu) * rstd * lng[n] + lnb[n];
    }
}

// ---------------- classifier + entity bump ----------------
__global__ __launch_bounds__(288) void classifier_kernel(
    const float* __restrict__ Ws, const float* __restrict__ bs,
    const float* __restrict__ eb, float* __restrict__ out)
{
    __shared__ float cur[HID_];
    __shared__ float prv[HID_];
    __shared__ float lcur[NL_];
    __shared__ float lprv[NL_];

    const int row = blockIdx.x;
    const int s = row & (S_ - 1);
    const bool has_prev = (s > 0);
    const int tid = threadIdx.x;

    for (int i = tid; i < HID_; i += 288) cur[i] = g_h[(size_t)row * HID_ + i];
    if (has_prev)
        for (int i = tid; i < HID_; i += 288) prv[i] = g_h[(size_t)(row - 1) * HID_ + i];
    __syncthreads();

    const int w = tid >> 5;
    const int lane = tid & 31;

    float a = 0.f, ap = 0.f;
    for (int d = lane; d < HID_; d += 32) {
        float wv = Ws[d * NL_ + w];
        a = fmaf(cur[d], wv, a);
        if (has_prev) ap = fmaf(prv[d], wv, ap);
    }
    #pragma unroll
    for (int off = 16; off > 0; off >>= 1) {
        a  += __shfl_down_sync(0xffffffffu, a, off);
        ap += __shfl_down_sync(0xffffffffu, ap, off);
    }
    if (lane == 0) {
        lcur[w] = a + bs[w];
        lprv[w] = ap + bs[w];
    }
    __syncthreads();

    if (tid == 0 && has_prev) {
        int am = 0;
        float best = lprv[0];
        #pragma unroll
        for (int l = 1; l < NL_; l++)
            if (lprv[l] > best) { best = lprv[l]; am = l; }
        if (am == 1) lcur[2] += 2.0f * eb[2];
    }
    __syncthreads();

    if (tid < NL_) out[(size_t)row * NL_ + tid] = lcur[tid];
}

// ---------------- launch ----------------
extern "C" void kernel_launch(void* const* d_in, const int* in_sizes, int n_in,
                              void* d_out, int out_size)
{
    const float* x   = (const float*)d_in[0];
    const float* Wq  = (const float*)d_in[1];
    const float* bq  = (const float*)d_in[2];
    const float* Wk  = (const float*)d_in[3];
    const float* bk  = (const float*)d_in[4];
    const float* Wv  = (const float*)d_in[5];
    const float* bv  = (const float*)d_in[6];
    const float* Wo  = (const float*)d_in[7];
    const float* bo  = (const float*)d_in[8];
    const float* lng = (const float*)d_in[9];
    const float* lnb = (const float*)d_in[10];
    const float* Ws  = (const float*)d_in[11];
    const float* bs  = (const float*)d_in[12];
    const float* eb  = (const float*)d_in[13];
    float* out = (float*)d_out;

    __nv_bfloat16 *xhi, *xlo, *wqkvThi, *wqkvTlo, *woThi, *woTlo;
    __nv_bfloat16 *qhi, *qlo, *khi, *klo, *vThi, *vTlo, *phi, *plo;
    float *gqkv, *gs, *gc, *gh;
    cudaGetSymbolAddress((void**)&xhi, g_xhi);
    cudaGetSymbolAddress((void**)&xlo, g_xlo);
    cudaGetSymbolAddress((void**)&wqkvThi, g_wqkvThi);
    cudaGetSymbolAddress((void**)&wqkvTlo, g_wqkvTlo);
    cudaGetSymbolAddress((void**)&woThi, g_woThi);
    cudaGetSymbolAddress((void**)&woTlo, g_woTlo);
    cudaGetSymbolAddress((void**)&qhi, g_qhi);
    cudaGetSymbolAddress((void**)&qlo, g_qlo);
    cudaGetSymbolAddress((void**)&khi, g_khi);
    cudaGetSymbolAddress((void**)&klo, g_klo);
    cudaGetSymbolAddress((void**)&vThi, g_vThi);
    cudaGetSymbolAddress((void**)&vTlo, g_vTlo);
    cudaGetSymbolAddress((void**)&phi, g_phi);
    cudaGetSymbolAddress((void**)&plo, g_plo);
    cudaGetSymbolAddress((void**)&gqkv, g_qkv);
    cudaGetSymbolAddress((void**)&gs, g_s);
    cudaGetSymbolAddress((void**)&gc, g_c);
    cudaGetSymbolAddress((void**)&gh, g_h);

    // dynamic smem: NTILE=128 -> 2*(2*10240 + 2*10240) = 81920
    //               NTILE=64  -> 2*(2*10240 + 2*5120)  = 61440
    const int SMEM_128 = 81920;
    const int SMEM_64  = 61440;
    cudaFuncSetAttribute(mma_gemm<0, 128>, cudaFuncAttributeMaxDynamicSharedMemorySize, SMEM_128);
    cudaFuncSetAttribute(mma_gemm<1, 128>, cudaFuncAttributeMaxDynamicSharedMemorySize, SMEM_128);
    cudaFuncSetAttribute(mma_gemm<2, 128>, cudaFuncAttributeMaxDynamicSharedMemorySize, SMEM_128);
    cudaFuncSetAttribute(mma_gemm<3, 64>,  cudaFuncAttributeMaxDynamicSharedMemorySize, SMEM_64);

    // 1. split x into bf16 hi/lo
    split4_kernel<<<(M_ROWS * HID_ / 4 + 255) / 256, 256>>>(x, xhi, xlo, M_ROWS * HID_ / 4);
    // 2. transpose + split weights
    wtrans_kernel<<<dim3(24, 24, 4), dim3(32, 8)>>>(Wq, Wk, Wv, Wo);
    // 3. fused QKV projection: [8192,768] @ [2304,768]^T -> g_qkv
    mma_gemm<0, 128><<<dim3(18, 64, 1), 256, SMEM_128>>>(
        xhi, xlo, HID_, wqkvThi, wqkvTlo, HID_, gqkv, 2304, HID_, bq, bk, bv, nullptr);
    // 4. split q,k
    split_qk_kernel<<<M_ROWS * 192 / 256, 256>>>();
    // 5. transpose + split v
    vtrans_kernel<<<dim3(16, 6, BH_), dim3(32, 8)>>>();
    // 6. scores per bh: [512,192] @ [512,192]^T
    mma_gemm<2, 128><<<dim3(4, 4, BH_), 256, SMEM_128>>>(
        qhi, qlo, HID_, khi, klo, HID_, gs, S_, HD_, nullptr, nullptr, nullptr, nullptr);
    // 7. softmax + split probs
    softmax_split_kernel<<<BH_ * S_, 256>>>();
    // 8. PV per bh: [512,512] @ [192,512]^T
    mma_gemm<3, 64><<<dim3(3, 4, BH_), 256, SMEM_64>>>(
        phi, plo, S_, vThi, vTlo, S_, gc, HID_, S_, nullptr, nullptr, nullptr, nullptr);
    // 9. split ctx (reuse q hi/lo buffers; q no longer needed)
    split4_kernel<<<(M_ROWS * HID_ / 4 + 255) / 256, 256>>>(gc, qhi, qlo, M_ROWS * HID_ / 4);
    // 10. O projection + bias + residual -> g_h
    mma_gemm<1, 128><<<dim3(6, 64, 1), 256, SMEM_128>>>(
        qhi, qlo, HID_, woThi, woTlo, HID_, gh, HID_, HID_, bo, nullptr, nullptr, x);
    // 11. layernorm
    layernorm_kernel<<<M_ROWS, 256>>>(lng, lnb);
    // 12. classifier + entity bump
    classifier_kernel<<<M_ROWS, 288>>>(Ws, bs, eb, out);
}

// round 5
// speedup vs baseline: 2.5619x; 1.8048x over previous
#include <cuda_runtime.h>
#include <cuda_bf16.h>
#include <cstdint>
#include <math.h>

// ---------------- problem constants ----------------
#define B_   16
#define S_   512
#define HID_ 768
#define NH_  4
#define HD_  192
#define NL_  9
#define M_ROWS (B_ * S_)   // 8192
#define BH_ (B_ * NH_)     // 64
#define INV_SQRT_D 0.07216878364870323f

// ---------------- mma helpers (sm_80-compatible PTX only) ----------------
__device__ __forceinline__ uint32_t smem_to_u32(const void* p) {
    uint32_t a;
    asm("{ .reg .u64 t; cvta.to.shared.u64 t, %1; cvt.u32.u64 %0, t; }" : "=r"(a) : "l"(p));
    return a;
}
__device__ __forceinline__ void ldsm_x4(uint32_t* r, uint32_t addr) {
    asm volatile("ldmatrix.sync.aligned.m8n8.x4.shared.b16 {%0,%1,%2,%3}, [%4];"
        : "=r"(r[0]), "=r"(r[1]), "=r"(r[2]), "=r"(r[3]) : "r"(addr));
}
__device__ __forceinline__ void ldsm_x4_t(uint32_t* r, uint32_t addr) {
    asm volatile("ldmatrix.sync.aligned.m8n8.x4.trans.shared.b16 {%0,%1,%2,%3}, [%4];"
        : "=r"(r[0]), "=r"(r[1]), "=r"(r[2]), "=r"(r[3]) : "r"(addr));
}
__device__ __forceinline__ void mma16816(float* d, const uint32_t* a, const uint32_t* b) {
    asm volatile("mma.sync.aligned.m16n8k16.row.col.f32.bf16.bf16.f32 "
        "{%0,%1,%2,%3}, {%4,%5,%6,%7}, {%8,%9}, {%0,%1,%2,%3};"
        : "+f"(d[0]), "+f"(d[1]), "+f"(d[2]), "+f"(d[3])
        : "r"(a[0]), "r"(a[1]), "r"(a[2]), "r"(a[3]), "r"(b[0]), "r"(b[1]));
}

// ---------------- device scratch ----------------
__device__ __nv_bfloat16 g_xhi[M_ROWS * HID_],  g_xlo[M_ROWS * HID_];
__device__ __nv_bfloat16 g_wqkvThi[3 * HID_ * HID_], g_wqkvTlo[3 * HID_ * HID_];
__device__ __nv_bfloat16 g_woThi[HID_ * HID_],  g_woTlo[HID_ * HID_];
__device__ __nv_bfloat16 g_qhi[M_ROWS * HID_], g_qlo[M_ROWS * HID_];
__device__ __nv_bfloat16 g_khi[M_ROWS * HID_], g_klo[M_ROWS * HID_];
__device__ __nv_bfloat16 g_vhi[M_ROWS * HID_], g_vlo[M_ROWS * HID_];   // natural [s][d]
__device__ float         g_s[(size_t)BH_ * S_ * S_];
__device__ __nv_bfloat16 g_phi[(size_t)BH_ * S_ * S_], g_plo[(size_t)BH_ * S_ * S_];
__device__ __nv_bfloat16 g_chi[M_ROWS * HID_], g_clo[M_ROWS * HID_];
__device__ float         g_h[M_ROWS * HID_];
__device__ float         g_logits[M_ROWS * NL_];

__device__ __forceinline__ void split_bf(float v, __nv_bfloat16& hi, __nv_bfloat16& lo) {
    hi = __float2bfloat16(v);
    lo = __float2bfloat16(v - __bfloat162float(hi));
}
__device__ __forceinline__ void split_pair_store(
    float v0, float v1, __nv_bfloat16* dh, __nv_bfloat16* dl)
{
    __nv_bfloat16 h0, l0, h1, l1;
    split_bf(v0, h0, l0);
    split_bf(v1, h1, l1);
    *(__nv_bfloat162*)dh = __nv_bfloat162(h0, h1);
    *(__nv_bfloat162*)dl = __nv_bfloat162(l0, l1);
}

// ---------------- input conversion kernels ----------------
__global__ __launch_bounds__(256) void split4_kernel(
    const float* __restrict__ src, __nv_bfloat16* __restrict__ hi,
    __nv_bfloat16* __restrict__ lo, int n4)
{
    int i = blockIdx.x * 256 + threadIdx.x;
    if (i >= n4) return;
    float4 v = ((const float4*)src)[i];
    __nv_bfloat16 h, l;
    split_bf(v.x, h, l); hi[i*4+0] = h; lo[i*4+0] = l;
    split_bf(v.y, h, l); hi[i*4+1] = h; lo[i*4+1] = l;
    split_bf(v.z, h, l); hi[i*4+2] = h; lo[i*4+2] = l;
    split_bf(v.w, h, l); hi[i*4+3] = h; lo[i*4+3] = l;
}

// weight transpose + split: z in {0,1,2}->qkvT combined, 3->woT
__global__ void wtrans_kernel(const float* __restrict__ Wq, const float* __restrict__ Wk,
                              const float* __restrict__ Wv, const float* __restrict__ Wo)
{
    __shared__ float tl[32][33];
    const int z = blockIdx.z;
    const float* W = (z == 0) ? Wq : (z == 1) ? Wk : (z == 2) ? Wv : Wo;
    const int n0 = blockIdx.x * 32, k0 = blockIdx.y * 32;
    const int tx = threadIdx.x, ty = threadIdx.y;  // (32,8)
    #pragma unroll
    for (int i = 0; i < 4; i++) {
        int k = ty + i * 8;
        tl[k][tx] = W[(size_t)(k0 + k) * HID_ + n0 + tx];
    }
    __syncthreads();
    #pragma unroll
    for (int i = 0; i < 4; i++) {
        int nloc = ty + i * 8;
        float v = tl[tx][nloc];
        __nv_bfloat16 h, l; split_bf(v, h, l);
        if (z < 3) {
            size_t o = (size_t)(z * HID_ + n0 + nloc) * HID_ + k0 + tx;
            g_wqkvThi[o] = h; g_wqkvTlo[o] = l;
        } else {
            size_t o = (size_t)(n0 + nloc) * HID_ + k0 + tx;
            g_woThi[o] = h; g_woTlo[o] = l;
        }
    }
}

// ---------------- split-bf16 mma.sync GEMM (NT: B is [n][k]) ----------------
// Block 128x128, 8 warps 2x4, warp tile 64x32, k-chunk 32.
// MODE 0: QKV proj -> writes q/k/v bf16 hi/lo with bias fused
// MODE 1: O proj -> fp32 g_h with bias + residual
// MODE 2: scores -> fp32 g_s with rel-bias epilogue (batched over bh)
template<int MODE>
__global__ __launch_bounds__(256) void mma_gemm(
    const __nv_bfloat16* __restrict__ Ahi, const __nv_bfloat16* __restrict__ Alo, int lda,
    const __nv_bfloat16* __restrict__ Bhi, const __nv_bfloat16* __restrict__ Blo, int ldb,
    float* __restrict__ C, int ldc, int K,
    const float* __restrict__ bb0, const float* __restrict__ bb1,
    const float* __restrict__ bb2, const float* __restrict__ resid)
{
    constexpr int ASZ  = 128 * 40 * 2;   // bytes per A (hi or lo) stage
    constexpr int BSZ  = 128 * 40 * 2;
    constexpr int STAGE = 2 * ASZ + 2 * BSZ;

    extern __shared__ char smem[];
    const uint32_t sbase = smem_to_u32(smem);
    const int tid  = threadIdx.x;
    const int lane = tid & 31;
    const int wid  = tid >> 5;
    const int wm   = (wid >> 2) * 64;
    const int wn   = (wid & 3) * 32;

    size_t aoff = 0, boff = 0, coff = 0;
    if (MODE == 2) {
        int bh = blockIdx.z, b = bh >> 2, h = bh & 3;
        aoff = (size_t)b * S_ * HID_ + h * HD_;  boff = aoff;
        coff = (size_t)bh * S_ * S_;
    }

    const int bm = blockIdx.y * 128;
    const int bn = blockIdx.x * 128;

    const __nv_bfloat16* Ah = Ahi + aoff + (size_t)bm * lda;
    const __nv_bfloat16* Al = Alo + aoff + (size_t)bm * lda;
    const __nv_bfloat16* Bh = Bhi + boff + (size_t)bn * ldb;
    const __nv_bfloat16* Bl = Blo + boff + (size_t)bn * ldb;

    const int lr = tid >> 2;              // 0..63
    const int lc = (tid & 3) * 8;

    float acc[4][4][4];
    #pragma unroll
    for (int i = 0; i < 4; i++)
        #pragma unroll
        for (int j = 0; j < 4; j++)
            #pragma unroll
            for (int u = 0; u < 4; u++) acc[i][j][u] = 0.f;

    const int nt = K >> 5;
    uint4 rah[2], ral[2], rbh[2], rbl[2];

    rah[0] = *(const uint4*)(Ah + (size_t)lr * lda + lc);
    rah[1] = *(const uint4*)(Ah + (size_t)(lr + 64) * lda + lc);
    ral[0] = *(const uint4*)(Al + (size_t)lr * lda + lc);
    ral[1] = *(const uint4*)(Al + (size_t)(lr + 64) * lda + lc);
    rbh[0] = *(const uint4*)(Bh + (size_t)lr * ldb + lc);
    rbh[1] = *(const uint4*)(Bh + (size_t)(lr + 64) * ldb + lc);
    rbl[0] = *(const uint4*)(Bl + (size_t)lr * ldb + lc);
    rbl[1] = *(const uint4*)(Bl + (size_t)(lr + 64) * ldb + lc);
    {
        char* st = smem;
        *(uint4*)(st + lr * 80 + lc * 2) = rah[0];
        *(uint4*)(st + (lr + 64) * 80 + lc * 2) = rah[1];
        *(uint4*)(st + ASZ + lr * 80 + lc * 2) = ral[0];
        *(uint4*)(st + ASZ + (lr + 64) * 80 + lc * 2) = ral[1];
        *(uint4*)(st + 2 * ASZ + lr * 80 + lc * 2) = rbh[0];
        *(uint4*)(st + 2 * ASZ + (lr + 64) * 80 + lc * 2) = rbh[1];
        *(uint4*)(st + 2 * ASZ + BSZ + lr * 80 + lc * 2) = rbl[0];
        *(uint4*)(st + 2 * ASZ + BSZ + (lr + 64) * 80 + lc * 2) = rbl[1];
    }
    __syncthreads();

    for (int t = 0; t < nt; ++t) {
        if (t + 1 < nt) {
            const __nv_bfloat16* Ahn = Ah + (t + 1) * 32;
            const __nv_bfloat16* Aln = Al + (t + 1) * 32;
            const __nv_bfloat16* Bhn = Bh + (t + 1) * 32;
            const __nv_bfloat16* Bln = Bl + (t + 1) * 32;
            rah[0] = *(const uint4*)(Ahn + (size_t)lr * lda + lc);
            rah[1] = *(const uint4*)(Ahn + (size_t)(lr + 64) * lda + lc);
            ral[0] = *(const uint4*)(Aln + (size_t)lr * lda + lc);
            ral[1] = *(const uint4*)(Aln + (size_t)(lr + 64) * lda + lc);
            rbh[0] = *(const uint4*)(Bhn + (size_t)lr * ldb + lc);
            rbh[1] = *(const uint4*)(Bhn + (size_t)(lr + 64) * ldb + lc);
            rbl[0] = *(const uint4*)(Bln + (size_t)lr * ldb + lc);
            rbl[1] = *(const uint4*)(Bln + (size_t)(lr + 64) * ldb + lc);
        }
        {
            const uint32_t aHiB = sbase + (t & 1) * STAGE;
            const uint32_t aLoB = aHiB + ASZ;
            const uint32_t bHiB = aHiB + 2 * ASZ;
            const uint32_t bLoB = bHiB + BSZ;
            #pragma unroll
            for (int ks = 0; ks < 2; ++ks) {
                const int k0 = ks * 16;
                uint32_t ah[4][4], al[4][4];
                const uint32_t arow = wm + (lane & 15);
                const uint32_t acol = k0 + ((lane >> 4) << 3);
                #pragma unroll
                for (int im = 0; im < 4; im++) {
                    uint32_t off = (arow + im * 16) * 80 + acol * 2;
                    ldsm_x4(ah[im], aHiB + off);
                    ldsm_x4(al[im], aLoB + off);
                }
                uint32_t bhf[2][4], blf[2][4];
                const uint32_t brow = wn + (lane & 7) + ((lane >> 4) << 3);
                const uint32_t bcol = k0 + (((lane >> 3) & 1) << 3);
                #pragma unroll
                for (int ib = 0; ib < 2; ib++) {
                    uint32_t off = (brow + ib * 16) * 80 + bcol * 2;
                    ldsm_x4(bhf[ib], bHiB + off);
                    ldsm_x4(blf[ib], bLoB + off);
                }
                #pragma unroll
                for (int im = 0; im < 4; im++)
                    #pragma unroll
                    for (int in = 0; in < 4; in++) {
                        const uint32_t* bh2 = &bhf[in >> 1][(in & 1) * 2];
                        const uint32_t* bl2 = &blf[in >> 1][(in & 1) * 2];
                        mma16816(acc[im][in], ah[im], bh2);
                        mma16816(acc[im][in], ah[im], bl2);
                        mma16816(acc[im][in], al[im], bh2);
                    }
            }
        }
        if (t + 1 < nt) {
            char* st = smem + ((t + 1) & 1) * STAGE;
            *(uint4*)(st + lr * 80 + lc * 2) = rah[0];
            *(uint4*)(st + (lr + 64) * 80 + lc * 2) = rah[1];
            *(uint4*)(st + ASZ + lr * 80 + lc * 2) = ral[0];
            *(uint4*)(st + ASZ + (lr + 64) * 80 + lc * 2) = ral[1];
            *(uint4*)(st + 2 * ASZ + lr * 80 + lc * 2) = rbh[0];
            *(uint4*)(st + 2 * ASZ + (lr + 64) * 80 + lc * 2) = rbh[1];
            *(uint4*)(st + 2 * ASZ + BSZ + lr * 80 + lc * 2) = rbl[0];
            *(uint4*)(st + 2 * ASZ + BSZ + (lr + 64) * 80 + lc * 2) = rbl[1];
            __syncthreads();
        }
    }

    // ---- epilogue ----
    #pragma unroll
    for (int im = 0; im < 4; im++) {
        #pragma unroll
        for (int in = 0; in < 4; in++) {
            const int gm0 = bm + wm + im * 16 + (lane >> 2);
            const int n   = bn + wn + in * 8 + ((lane & 3) << 1);
            float* d = acc[im][in];
            if (MODE == 0) {
                // bias + split -> q/k/v hi/lo
                #pragma unroll
                for (int half = 0; half < 2; half++) {
                    int gm = gm0 + half * 8;
                    float v0 = d[half * 2 + 0];
                    float v1 = d[half * 2 + 1];
                    int seg = (n >= 1536) ? 2 : (n >= 768) ? 1 : 0;
                    int col = n - seg * 768;
                    const float* bias = (seg == 0) ? bb0 : (seg == 1) ? bb1 : bb2;
                    v0 += bias[col];
                    v1 += bias[col + 1];
                    size_t o = (size_t)gm * HID_ + col;
                    __nv_bfloat16* dh = (seg == 0) ? &g_qhi[o] : (seg == 1) ? &g_khi[o] : &g_vhi[o];
                    __nv_bfloat16* dl = (seg == 0) ? &g_qlo[o] : (seg == 1) ? &g_klo[o] : &g_vlo[o];
                    split_pair_store(v0, v1, dh, dl);
                }
            } else if (MODE == 1) {
                #pragma unroll
                for (int half = 0; half < 2; half++) {
                    int gm = gm0 + half * 8;
                    float2 o;
                    o.x = d[half * 2 + 0] + bb0[n]     + resid[(size_t)gm * HID_ + n];
                    o.y = d[half * 2 + 1] + bb0[n + 1] + resid[(size_t)gm * HID_ + n + 1];
                    *(float2*)(C + (size_t)gm * ldc + n) = o;
                }
            } else {
                #pragma unroll
                for (int half = 0; half < 2; half++) {
                    int gm = gm0 + half * 8;
                    float2 o;
                    {
                        float dist = fabsf((float)(gm - n));
                        float relb = __expf(-0.1f * fminf(dist, 5.0f));
                        o.x = (d[half * 2 + 0] + relb) * INV_SQRT_D - 0.1f * dist;
                    }
                    {
                        float dist = fabsf((float)(gm - (n + 1)));
                        float relb = __expf(-0.1f * fminf(dist, 5.0f));
                        o.y = (d[half * 2 + 1] + relb) * INV_SQRT_D - 0.1f * dist;
                    }
                    *(float2*)(C + coff + (size_t)gm * ldc + n) = o;
                }
            }
        }
    }
}

// ---------------- PV GEMM: probs @ V, B natural [s][d] via trans ldmatrix ----
// Block 128x64, 8 warps 2x4, warp tile 64x16, k-chunk 32. Batched over bh.
__global__ __launch_bounds__(256) void mma_pv()
{
    constexpr int ASZ  = 128 * 40 * 2;   // 10240
    constexpr int BSZ  = 32 * 72 * 2;    // 4608
    constexpr int STAGE = 2 * ASZ + 2 * BSZ;  // 29696

    extern __shared__ char smem[];
    const uint32_t sbase = smem_to_u32(smem);
    const int tid  = threadIdx.x;
    const int lane = tid & 31;
    const int wid  = tid >> 5;
    const int wm   = (wid >> 2) * 64;
    const int wn   = (wid & 3) * 16;

    const int bh = blockIdx.z, b = bh >> 2, h = bh & 3;
    const size_t aoff = (size_t)bh * S_ * S_;
    const size_t voff = (size_t)b * S_ * HID_ + h * HD_;   // v natural layout
    const size_t coff = voff;                               // ctx same layout

    const int bm = blockIdx.y * 128;
    const int bn = blockIdx.x * 64;

    const __nv_bfloat16* Ah = g_phi + aoff + (size_t)bm * S_;
    const __nv_bfloat16* Al = g_plo + aoff + (size_t)bm * S_;
    const __nv_bfloat16* Bh = g_vhi + voff + bn;   // row k=s, col n=d
    const __nv_bfloat16* Bl = g_vlo + voff + bn;

    const int lr  = tid >> 2;         // A rows 0..63
    const int lc  = (tid & 3) * 8;
    const int lr2 = tid >> 3;         // B rows 0..31
    const int lc2 = (tid & 7) * 8;

    float acc[4][2][4];
    #pragma unroll
    for (int i = 0; i < 4; i++)
        #pragma unroll
        for (int j = 0; j < 2; j++)
            #pragma unroll
            for (int u = 0; u < 4; u++) acc[i][j][u] = 0.f;

    const int nt = S_ >> 5;   // 16
    uint4 rah[2], ral[2], rbh1, rbl1;

    rah[0] = *(const uint4*)(Ah + (size_t)lr * S_ + lc);
    rah[1] = *(const uint4*)(Ah + (size_t)(lr + 64) * S_ + lc);
    ral[0] = *(const uint4*)(Al + (size_t)lr * S_ + lc);
    ral[1] = *(const uint4*)(Al + (size_t)(lr + 64) * S_ + lc);
    rbh1   = *(const uint4*)(Bh + (size_t)lr2 * HID_ + lc2);
    rbl1   = *(const uint4*)(Bl + (size_t)lr2 * HID_ + lc2);
    {
        char* st = smem;
        *(uint4*)(st + lr * 80 + lc * 2) = rah[0];
        *(uint4*)(st + (lr + 64) * 80 + lc * 2) = rah[1];
        *(uint4*)(st + ASZ + lr * 80 + lc * 2) = ral[0];
        *(uint4*)(st + ASZ + (lr + 64) * 80 + lc * 2) = ral[1];
        *(uint4*)(st + 2 * ASZ + lr2 * 144 + lc2 * 2) = rbh1;
        *(uint4*)(st + 2 * ASZ + BSZ + lr2 * 144 + lc2 * 2) = rbl1;
    }
    __syncthreads();

    for (int t = 0; t < nt; ++t) {
        if (t + 1 < nt) {
            rah[0] = *(const uint4*)(Ah + (size_t)lr * S_ + (t + 1) * 32 + lc);
            rah[1] = *(const uint4*)(Ah + (size_t)(lr + 64) * S_ + (t + 1) * 32 + lc);
            ral[0] = *(const uint4*)(Al + (size_t)lr * S_ + (t + 1) * 32 + lc);
            ral[1] = *(const uint4*)(Al + (size_t)(lr + 64) * S_ + (t + 1) * 32 + lc);
            rbh1   = *(const uint4*)(Bh + (size_t)((t + 1) * 32 + lr2) * HID_ + lc2);
            rbl1   = *(const uint4*)(Bl + (size_t)((t + 1) * 32 + lr2) * HID_ + lc2);
        }
        {
            const uint32_t aHiB = sbase + (t & 1) * STAGE;
            const uint32_t aLoB = aHiB + ASZ;
            const uint32_t bHiB = aHiB + 2 * ASZ;
            const uint32_t bLoB = bHiB + BSZ;
            #pragma unroll
            for (int ks = 0; ks < 2; ++ks) {
                const int k0 = ks * 16;
                uint32_t ah[4][4], al[4][4];
                const uint32_t arow = wm + (lane & 15);
                const uint32_t acol = k0 + ((lane >> 4) << 3);
                #pragma unroll
                for (int im = 0; im < 4; im++) {
                    uint32_t off = (arow + im * 16) * 80 + acol * 2;
                    ldsm_x4(ah[im], aHiB + off);
                    ldsm_x4(al[im], aLoB + off);
                }
                // trans-B: smem [k][n]; m0=(k0-7,n0-7) m1=(k8-15,n0-7) m2=(k0-7,n8-15) m3=(k8-15,n8-15)
                uint32_t bhf[4], blf[4];
                const uint32_t bkrow = k0 + (lane & 7) + (((lane >> 3) & 1) << 3);
                const uint32_t bncol = wn + ((lane >> 4) << 3);
                {
                    uint32_t off = bkrow * 144 + bncol * 2;
                    ldsm_x4_t(bhf, bHiB + off);
                    ldsm_x4_t(blf, bLoB + off);
                }
                #pragma unroll
                for (int im = 0; im < 4; im++)
                    #pragma unroll
                    for (int in = 0; in < 2; in++) {
                        const uint32_t* bh2 = &bhf[in * 2];
                        const uint32_t* bl2 = &blf[in * 2];
                        mma16816(acc[im][in], ah[im], bh2);
                        mma16816(acc[im][in], ah[im], bl2);
                        mma16816(acc[im][in], al[im], bh2);
                    }
            }
        }
        if (t + 1 < nt) {
            char* st = smem + ((t + 1) & 1) * STAGE;
            *(uint4*)(st + lr * 80 + lc * 2) = rah[0];
            *(uint4*)(st + (lr + 64) * 80 + lc * 2) = rah[1];
            *(uint4*)(st + ASZ + lr * 80 + lc * 2) = ral[0];
            *(uint4*)(st + ASZ + (lr + 64) * 80 + lc * 2) = ral[1];
            *(uint4*)(st + 2 * ASZ + lr2 * 144 + lc2 * 2) = rbh1;
            *(uint4*)(st + 2 * ASZ + BSZ + lr2 * 144 + lc2 * 2) = rbl1;
            __syncthreads();
        }
    }

    // epilogue: ctx -> bf16 hi/lo
    #pragma unroll
    for (int im = 0; im < 4; im++) {
        #pragma unroll
        for (int in = 0; in < 2; in++) {
            const int gm0 = bm + wm + im * 16 + (lane >> 2);
            const int n   = bn + wn + in * 8 + ((lane & 3) << 1);
            float* d = acc[im][in];
            #pragma unroll
            for (int half = 0; half < 2; half++) {
                int gm = gm0 + half * 8;
                size_t o = coff + (size_t)gm * HID_ + n;
                split_pair_store(d[half * 2 + 0], d[half * 2 + 1], &g_chi[o], &g_clo[o]);
            }
        }
    }
}

// ---------------- warp-per-row softmax + split ----------------
__global__ __launch_bounds__(256) void softmax_split_kernel()
{
    const int tid = threadIdx.x;
    const int row = blockIdx.x * 8 + (tid >> 5);
    const int lane = tid & 31;
    const float* p = g_s + (size_t)row * S_;

    float4 v[4];
    float mx = -1e30f;
    #pragma unroll
    for (int i = 0; i < 4; i++) {
        v[i] = *(const float4*)(p + i * 128 + lane * 4);
        mx = fmaxf(mx, fmaxf(fmaxf(v[i].x, v[i].y), fmaxf(v[i].z, v[i].w)));
    }
    #pragma unroll
    for (int off = 16; off > 0; off >>= 1)
        mx = fmaxf(mx, __shfl_xor_sync(0xffffffffu, mx, off));

    float sum = 0.f;
    #pragma unroll
    for (int i = 0; i < 4; i++) {
        v[i].x = __expf(v[i].x - mx); v[i].y = __expf(v[i].y - mx);
        v[i].z = __expf(v[i].z - mx); v[i].w = __expf(v[i].w - mx);
        sum += v[i].x + v[i].y + v[i].z + v[i].w;
    }
    #pragma unroll
    for (int off = 16; off > 0; off >>= 1)
        sum += __shfl_xor_sync(0xffffffffu, sum, off);
    float inv = 1.0f / sum;

    size_t o = (size_t)row * S_;
    #pragma unroll
    for (int i = 0; i < 4; i++) {
        size_t c = o + i * 128 + lane * 4;
        __nv_bfloat16 h0, l0, h1, l1, h2, l2, h3, l3;
        split_bf(v[i].x * inv, h0, l0);
        split_bf(v[i].y * inv, h1, l1);
        split_bf(v[i].z * inv, h2, l2);
        split_bf(v[i].w * inv, h3, l3);
        *(__nv_bfloat162*)(g_phi + c)     = __nv_bfloat162(h0, h1);
        *(__nv_bfloat162*)(g_phi + c + 2) = __nv_bfloat162(h2, h3);
        *(__nv_bfloat162*)(g_plo + c)     = __nv_bfloat162(l0, l1);
        *(__nv_bfloat162*)(g_plo + c + 2) = __nv_bfloat162(l2, l3);
    }
}

// ---------------- LayerNorm ----------------
__global__ __launch_bounds__(256) void layernorm_kernel(
    const float* __restrict__ lng, const float* __restrict__ lnb)
{
    __shared__ float sh[HID_];
    __shared__ float red[256];
    const int row = blockIdx.x;
    float* p = g_h + (size_t)row * HID_;
    const int tid = threadIdx.x;

    float s = 0.f;
    #pragma unroll
    for (int i = 0; i < 3; i++) {
        float v = p[tid + i * 256];
        sh[tid + i * 256] = v;
        s += v;
    }
    red[tid] = s;
    __syncthreads();
    for (int off = 128; off > 0; off >>= 1) {
        if (tid < off) red[tid] += red[tid + off];
        __syncthreads();
    }
    float mu = red[0] * (1.0f / HID_);
    __syncthreads();

    float sq = 0.f;
    #pragma unroll
    for (int i = 0; i < 3; i++) {
        float d = sh[tid + i * 256] - mu;
        sq += d * d;
    }
    red[tid] = sq;
    __syncthreads();
    for (int off = 128; off > 0; off >>= 1) {
        if (tid < off) red[tid] += red[tid + off];
        __syncthreads();
    }
    float rstd = rsqrtf(red[0] * (1.0f / HID_) + 1e-5f);
    __syncthreads();

    #pragma unroll
    for (int i = 0; i < 3; i++) {
        int n = tid + i * 256;
        p[n] = (sh[n] - mu) * rstd * lng[n] + lnb[n];
    }
}

// ---------------- classifier (logits only) ----------------
__global__ __launch_bounds__(288) void classifier_kernel(
    const float* __restrict__ Ws, const float* __restrict__ bs)
{
    __shared__ float cur[HID_];
    const int row = blockIdx.x;
    const int tid = threadIdx.x;

    for (int i = tid; i < HID_; i += 288) cur[i] = g_h[(size_t)row * HID_ + i];
    __syncthreads();

    const int w = tid >> 5;
    const int lane = tid & 31;

    float a = 0.f;
    for (int d = lane; d < HID_; d += 32)
        a = fmaf(cur[d], Ws[d * NL_ + w], a);
    #pragma unroll
    for (int off = 16; off > 0; off >>= 1)
        a += __shfl_down_sync(0xffffffffu, a, off);
    if (lane == 0)
        g_logits[(size_t)row * NL_ + w] = a + bs[w];
}

// ---------------- entity-bias bump + final write ----------------
__global__ __launch_bounds__(256) void bump_kernel(
    const float* __restrict__ eb, float* __restrict__ out)
{
    int row = blockIdx.x * 256 + threadIdx.x;
    if (row >= M_ROWS) return;
    float add = 0.f;
    if (row & (S_ - 1)) {
        const float* lp = g_logits + (size_t)(row - 1) * NL_;
        int am = 0; float best = lp[0];
        #pragma unroll
        for (int l = 1; l < NL_; l++)
            if (lp[l] > best) { best = lp[l]; am = l; }
        if (am == 1) add = 2.0f * eb[2];
    }
    const float* lc = g_logits + (size_t)row * NL_;
    #pragma unroll
    for (int l = 0; l < NL_; l++)
        out[(size_t)row * NL_ + l] = lc[l] + ((l == 2) ? add : 0.f);
}

// ---------------- launch ----------------
extern "C" void kernel_launch(void* const* d_in, const int* in_sizes, int n_in,
                              void* d_out, int out_size)
{
    const float* x   = (const float*)d_in[0];
    const float* Wq  = (const float*)d_in[1];
    const float* bq  = (const float*)d_in[2];
    const float* Wk  = (const float*)d_in[3];
    const float* bk  = (const float*)d_in[4];
    const float* Wv  = (const float*)d_in[5];
    const float* bv  = (const float*)d_in[6];
    const float* Wo  = (const float*)d_in[7];
    const float* bo  = (const float*)d_in[8];
    const float* lng = (const float*)d_in[9];
    const float* lnb = (const float*)d_in[10];
    const float* Ws  = (const float*)d_in[11];
    const float* bs  = (const float*)d_in[12];
    const float* eb  = (const float*)d_in[13];
    float* out = (float*)d_out;

    __nv_bfloat16 *xhi, *xlo, *wqkvThi, *wqkvTlo, *woThi, *woTlo, *chi, *clo;
    float *gs, *gh;
    cudaGetSymbolAddress((void**)&xhi, g_xhi);
    cudaGetSymbolAddress((void**)&xlo, g_xlo);
    cudaGetSymbolAddress((void**)&wqkvThi, g_wqkvThi);
    cudaGetSymbolAddress((void**)&wqkvTlo, g_wqkvTlo);
    cudaGetSymbolAddress((void**)&woThi, g_woThi);
    cudaGetSymbolAddress((void**)&woTlo, g_woTlo);
    cudaGetSymbolAddress((void**)&chi, g_chi);
    cudaGetSymbolAddress((void**)&clo, g_clo);
    cudaGetSymbolAddress((void**)&gs, g_s);
    cudaGetSymbolAddress((void**)&gh, g_h);

    const int SMEM_G  = 81920;   // 2 * (2*10240 + 2*10240)
    const int SMEM_PV = 59392;   // 2 * (2*10240 + 2*4608)
    cudaFuncSetAttribute(mma_gemm<0>, cudaFuncAttributeMaxDynamicSharedMemorySize, SMEM_G);
    cudaFuncSetAttribute(mma_gemm<1>, cudaFuncAttributeMaxDynamicSharedMemorySize, SMEM_G);
    cudaFuncSetAttribute(mma_gemm<2>, cudaFuncAttributeMaxDynamicSharedMemorySize, SMEM_G);
    cudaFuncSetAttribute(mma_pv,      cudaFuncAttributeMaxDynamicSharedMemorySize, SMEM_PV);

    __nv_bfloat16 *qhi, *qlo, *khi, *klo;
    cudaGetSymbolAddress((void**)&qhi, g_qhi);
    cudaGetSymbolAddress((void**)&qlo, g_qlo);
    cudaGetSymbolAddress((void**)&khi, g_khi);
    cudaGetSymbolAddress((void**)&klo, g_klo);

    // 1. split x
    split4_kernel<<<(M_ROWS * HID_ / 4 + 255) / 256, 256>>>(x, xhi, xlo, M_ROWS * HID_ / 4);
    // 2. transpose + split weights
    wtrans_kernel<<<dim3(24, 24, 4), dim3(32, 8)>>>(Wq, Wk, Wv, Wo);
    // 3. fused QKV projection -> bf16 hi/lo q,k,v directly (bias fused)
    mma_gemm<0><<<dim3(18, 64, 1), 256, SMEM_G>>>(
        xhi, xlo, HID_, wqkvThi, wqkvTlo, HID_, nullptr, 0, HID_, bq, bk, bv, nullptr);
    // 4. scores per bh -> fp32 g_s (rel-bias fused)
    mma_gemm<2><<<dim3(4, 4, BH_), 256, SMEM_G>>>(
        qhi, qlo, HID_, khi, klo, HID_, gs, S_, HD_, nullptr, nullptr, nullptr, nullptr);
    // 5. warp softmax -> bf16 hi/lo probs
    softmax_split_kernel<<<BH_ * S_ / 8, 256>>>();
    // 6. PV per bh -> bf16 hi/lo ctx directly
    mma_pv<<<dim3(3, 4, BH_), 256, SMEM_PV>>>();
    // 7. O projection + bias + residual -> g_h
    mma_gemm<1><<<dim3(6, 64, 1), 256, SMEM_G>>>(
        chi, clo, HID_, woThi, woTlo, HID_, gh, HID_, HID_, bo, nullptr, nullptr, x);
    // 8. layernorm
    layernorm_kernel<<<M_ROWS, 256>>>(lng, lnb);
    // 9. classifier logits
    classifier_kernel<<<M_ROWS, 288>>>(Ws, bs);
    // 10. entity bump + final write
    bump_kernel<<<(M_ROWS + 255) / 256, 256>>>(eb, out);
}